// round 9
// baseline (speedup 1.0000x reference)
#include <cuda_runtime.h>
#include <cuda_fp16.h>
#include <math.h>
#include <stdint.h>

#define BB 8
#define CIN 256
#define COUT 256
#define HH 64
#define WW 64
#define HWP 4096
#define KKN 9

typedef unsigned long long u64;

// ---------------- low-level helpers ----------------
__device__ __forceinline__ u64 pack2(float lo, float hi) {
    u64 r; asm("mov.b64 %0, {%1,%2};" : "=l"(r) : "f"(lo), "f"(hi)); return r;
}
__device__ __forceinline__ void unpack2(u64 v, float &lo, float &hi) {
    asm("mov.b64 {%0,%1}, %2;" : "=f"(lo), "=f"(hi) : "l"(v));
}
__device__ __forceinline__ u64 ffma2(u64 a, u64 b, u64 c) {
    u64 d; asm("fma.rn.f32x2 %0, %1, %2, %3;" : "=l"(d) : "l"(a), "l"(b), "l"(c)); return d;
}
__device__ __forceinline__ uint32_t smem_u32(const void *p) {
    uint32_t a; asm("{ .reg .u64 t; cvta.to.shared.u64 t, %1; cvt.u32.u64 %0, t; }" : "=r"(a) : "l"(p));
    return a;
}

#define CP_ASYNC16(dst, src) \
    asm volatile("cp.async.cg.shared.global [%0], [%1], 16;" :: "r"(dst), "l"(src) : "memory")
#define CP_COMMIT() asm volatile("cp.async.commit_group;" ::: "memory")
#define CP_WAIT1() asm volatile("cp.async.wait_group 1;" ::: "memory")

#define LDSM_X4(r, addr) \
    asm volatile("ldmatrix.sync.aligned.m8n8.x4.shared.b16 {%0,%1,%2,%3}, [%4];" \
        : "=r"((r)[0]), "=r"((r)[1]), "=r"((r)[2]), "=r"((r)[3]) : "r"(addr))
#define LDSM_X2(r, addr) \
    asm volatile("ldmatrix.sync.aligned.m8n8.x2.shared.b16 {%0,%1}, [%2];" \
        : "=r"((r)[0]), "=r"((r)[1]) : "r"(addr))

#define MMA_FP16(d, a, b) \
    asm volatile("mma.sync.aligned.m16n8k16.row.col.f32.f16.f16.f32 " \
        "{%0,%1,%2,%3}, {%4,%5,%6,%7}, {%8,%9}, {%0,%1,%2,%3};" \
        : "+f"((d)[0]), "+f"((d)[1]), "+f"((d)[2]), "+f"((d)[3]) \
        : "r"((a)[0]), "r"((a)[1]), "r"((a)[2]), "r"((a)[3]), "r"((b)[0]), "r"((b)[1]))

#define SWZ(o) ((o) ^ (((o) >> 3) & 0x70))

// ---------------- scratch ----------------
__device__ __half g_xf[(size_t)BB * HWP * CIN];          // [b][p][c] fp16
__device__ __half g_wf[KKN * COUT * CIN];                // [kk][o][c] fp16
__device__ __half g_y[(size_t)KKN * BB * HWP * COUT];    // [kk][b][p][o] fp16
__device__ float  g_ompart[4][BB * 27 * HWP];            // 4 c-splits of 64
__device__ int    g_tilectr = 0;
__device__ int    g_donectr = 0;

// ================= 1) prep: transpose + w conversion ============
#define NB_TR 8192
#define NB_WS 144
#define NB_PREP (NB_TR + NB_WS)

__global__ void __launch_bounds__(256) k_prep(const float *__restrict__ x,
                                              const float *__restrict__ wdcn) {
    __shared__ float tile[32][33];
    int blk = blockIdx.x;
    int t = threadIdx.x;

    if (blk < NB_TR) {
        int p0 = (blk & 127) * 32;
        int c0 = ((blk >> 7) & 7) * 32;
        int b = blk >> 10;
        int tx = t & 31, ty = t >> 5;
        const float *src = x + (size_t)b * CIN * HWP;
#pragma unroll
        for (int k = 0; k < 32; k += 8)
            tile[ty + k][tx] = src[(size_t)(c0 + ty + k) * HWP + p0 + tx];
        __syncthreads();
        __half *dh = g_xf + (size_t)b * HWP * CIN;
#pragma unroll
        for (int k = 0; k < 32; k += 8)
            dh[(size_t)(p0 + ty + k) * CIN + c0 + tx] = __float2half_rn(tile[tx][ty + k]);
    } else {
        int blkL = blk - NB_TR;
        int base = blkL * 4096 + t;
#pragma unroll
        for (int k = 0; k < 16; k++) {
            int i = base + k * 256;
            int c = i % CIN;
            int o = (i / CIN) % COUT;
            int kk = i / (CIN * COUT);
            g_wf[i] = __float2half_rn(wdcn[(size_t)(o * CIN + c) * KKN + kk]);
        }
    }
}

// ================= 2) main: om-conv blocks + persistent fp16 GEMM ============
#define NB_OM 128
#define NGEMM 296
#define NT 4608
#define KC 64
#define STAGE_BYTES 32768
#define X_OFF 0
#define W_OFF 16384
#define SM_TOT (3 * STAGE_BYTES)

struct TileInfo {
    const __half *xf, *wf;
    size_t yoff;
};
__device__ __forceinline__ TileInfo tile_decode(int ti) {
    int inner = ti % 18;
    int outer = ti / 18;
    int b = outer >> 5;
    int p0 = (outer & 31) * 128;
    int kk = inner >> 1;
    int o0 = (inner & 1) * 128;
    TileInfo r;
    r.xf = g_xf + ((size_t)b * HWP + p0) * CIN;
    r.wf = g_wf + ((size_t)kk * COUT + o0) * CIN;
    r.yoff = (((size_t)(kk * BB + b) * HWP + p0) * COUT) + o0;
    return r;
}

__global__ void __launch_bounds__(256, 2) k_main(const float *__restrict__ x,
                                                 const float *__restrict__ wom) {
    extern __shared__ __align__(16) char smem[];
    __shared__ int s_next;
    int t = threadIdx.x;

    if (blockIdx.x < NB_OM) {
        // ---------- om conv: 27ch 3x3, 4 pixels/thread, c-split 4 ----------
        int blk = blockIdx.x;
        int split = blk & 3;
        int b = (blk >> 2) & 7;
        int rb = blk >> 5;
        int s = t >> 6;
        int ox = t & 63;
        int y0 = rb * 16 + s * 4;

        u64 acc0[27], acc1[27];
#pragma unroll
        for (int i = 0; i < 27; i++) { acc0[i] = 0ULL; acc1[i] = 0ULL; }

        bool rowok[6]; int rowoff[6];
#pragma unroll
        for (int r = 0; r < 6; r++) {
            int y = y0 - 1 + r;
            rowok[r] = (y >= 0) && (y < HH);
            rowoff[r] = rowok[r] ? y * WW : 0;
        }
        bool colok[3]; int coloff[3];
#pragma unroll
        for (int c = 0; c < 3; c++) {
            int xx = ox - 1 + c;
            colok[c] = (xx >= 0) && (xx < WW);
            coloff[c] = colok[c] ? xx : 0;
        }

        int cbase = split * 64;
        const float *xb = x + (size_t)b * CIN * HWP;
        u64 *wshf = (u64 *)smem;

        for (int cc = 0; cc < 64; cc += 16) {
            __syncthreads();
            for (int j = t; j < 16 * 243; j += 256) {
                int oc = j / 144, rem = j % 144;
                float g = wom[(size_t)oc * 2304 + (size_t)(cbase + cc) * 9 + rem];
                wshf[(rem / 9) * 243 + oc * 9 + (rem % 9)] = pack2(g, g);
            }
            __syncthreads();
#pragma unroll 1
            for (int cil = 0; cil < 16; cil++) {
                const float *xc = xb + (size_t)(cbase + cc + cil) * HWP;
                float a[6][3];
#pragma unroll
                for (int r = 0; r < 6; r++)
#pragma unroll
                    for (int c = 0; c < 3; c++)
                        a[r][c] = (rowok[r] && colok[c]) ? __ldg(xc + rowoff[r] + coloff[c]) : 0.f;
                u64 pv0[9], pv1[9];
#pragma unroll
                for (int kk = 0; kk < 9; kk++) {
                    int ki = kk / 3, kj = kk % 3;
                    pv0[kk] = pack2(a[ki][kj], a[ki + 2][kj]);
                    pv1[kk] = pack2(a[ki + 1][kj], a[ki + 3][kj]);
                }
                const u64 *wrow = &wshf[cil * 243];
#pragma unroll
                for (int kk = 0; kk < 9; kk++)
#pragma unroll
                    for (int oc = 0; oc < 27; oc++) {
                        u64 w = wrow[oc * 9 + kk];
                        acc0[oc] = ffma2(pv0[kk], w, acc0[oc]);
                        acc1[oc] = ffma2(pv1[kk], w, acc1[oc]);
                    }
            }
        }

        float *dst = &g_ompart[split][(size_t)b * 27 * HWP];
#pragma unroll
        for (int oc = 0; oc < 27; oc++) {
            float l0, h0, l1, h1;
            unpack2(acc0[oc], l0, h0);
            unpack2(acc1[oc], l1, h1);
            size_t base = (size_t)oc * HWP + y0 * WW + ox;
            dst[base] = l0;
            dst[base + WW] = l1;
            dst[base + 2 * WW] = h0;
            dst[base + 3 * WW] = h1;
        }
        return;
    }

    // ---------- persistent GEMM, atomic tile grab, 3-stage ring ----------
    uint32_t sb = smem_u32(smem);
    int wid = t >> 5, lane = t & 31;

    int lsw4[4], lrow4[4], latom4[4];
#pragma unroll
    for (int k2 = 0; k2 < 4; k2++) {
        int idx = t + k2 * 256;
        lrow4[k2] = idx >> 3;
        latom4[k2] = idx & 7;
        lsw4[k2] = SWZ((idx >> 3) * 128 + (idx & 7) * 16);
    }

    int wp = wid >> 2;
    int wo = wid & 3;
    int abase = (wp * 64 + (lane & 15)) * 128 + ((lane >> 4) * 8) * 2;
    int bbase = (wo * 32 + (lane & 7)) * 128 + (((lane >> 3) & 1) * 8) * 2;

    // issue chunk c (0..3) of tile T into stage sg (predicate on)
#define ISSUE(T, c, sg, on) do { \
        uint32_t _stb = sb + (sg) * STAGE_BYTES; \
        if (on) { \
            int _c0 = (c) * KC; \
            _Pragma("unroll") \
            for (int k2 = 0; k2 < 4; k2++) { \
                size_t g = (size_t)lrow4[k2] * CIN + _c0 + latom4[k2] * 8; \
                CP_ASYNC16(_stb + X_OFF + lsw4[k2], (T).xf + g); \
                CP_ASYNC16(_stb + W_OFF + lsw4[k2], (T).wf + g); \
            } \
        } \
        CP_COMMIT(); \
    } while (0)

#define CONSUME(sg) do { \
        uint32_t stb = sb + (sg) * STAGE_BYTES; \
        _Pragma("unroll") \
        for (int ks = 0; ks < 4; ks++) { \
            uint32_t ah[4][4]; \
            _Pragma("unroll") \
            for (int mt = 0; mt < 4; mt++) \
                LDSM_X4(ah[mt], stb + X_OFF + SWZ(abase + mt * 2048 + ks * 32)); \
            uint32_t bh[4][2]; \
            _Pragma("unroll") \
            for (int nt = 0; nt < 4; nt++) \
                LDSM_X2(bh[nt], stb + W_OFF + SWZ(bbase + nt * 1024 + ks * 32)); \
            _Pragma("unroll") \
            for (int mt = 0; mt < 4; mt++) \
                _Pragma("unroll") \
                for (int nt = 0; nt < 4; nt++) \
                    MMA_FP16(d[mt][nt], ah[mt], bh[nt]); \
        } \
    } while (0)

    float d[4][4][4];
#pragma unroll
    for (int mt = 0; mt < 4; mt++)
#pragma unroll
        for (int nt = 0; nt < 4; nt++)
#pragma unroll
            for (int j = 0; j < 4; j++) d[mt][nt][j] = 0.f;

    if (t == 0) s_next = atomicAdd(&g_tilectr, 1);
    __syncthreads();
    int ti_cur = s_next;

    if (ti_cur < NT) {
        TileInfo tc = tile_decode(ti_cur);
        int s0 = 0;   // stage of current tile's chunk 0

        ISSUE(tc, 0, s0, true);
        ISSUE(tc, 1, (s0 + 1) % 3, true);

        for (;;) {
            int s1 = (s0 + 1) % 3, s2 = (s0 + 2) % 3;
            // j=0: consume c0
            CP_WAIT1(); __syncthreads();
            ISSUE(tc, 2, s2, true);
            CONSUME(s0);
            // j=1: consume c1
            CP_WAIT1(); __syncthreads();
            if (t == 0) s_next = atomicAdd(&g_tilectr, 1);
            ISSUE(tc, 3, s0, true);
            CONSUME(s1);
            // j=2: consume c2
            CP_WAIT1(); __syncthreads();
            int ti_nxt = s_next;
            TileInfo tn = tile_decode(ti_nxt < NT ? ti_nxt : 0);
            ISSUE(tn, 0, s1, ti_nxt < NT);
            CONSUME(s2);
            // j=3: consume c3
            CP_WAIT1(); __syncthreads();
            ISSUE(tn, 1, s2, ti_nxt < NT);
            CONSUME(s0);

            // epilogue: store this tile's result, reset accumulators
            __half *yo = g_y + tc.yoff;
#pragma unroll
            for (int mt = 0; mt < 4; mt++) {
                int r0 = wp * 64 + mt * 16 + (lane >> 2);
#pragma unroll
                for (int nt = 0; nt < 4; nt++) {
                    int c = wo * 32 + nt * 8 + (lane & 3) * 2;
                    *(__half2 *)(yo + (size_t)r0 * COUT + c) = __floats2half2_rn(d[mt][nt][0], d[mt][nt][1]);
                    *(__half2 *)(yo + (size_t)(r0 + 8) * COUT + c) = __floats2half2_rn(d[mt][nt][2], d[mt][nt][3]);
                    d[mt][nt][0] = 0.f; d[mt][nt][1] = 0.f; d[mt][nt][2] = 0.f; d[mt][nt][3] = 0.f;
                }
            }

            if (ti_nxt >= NT) break;
            tc = tn;
            s0 = s1;
        }
    }

    // self-resetting counters for graph replay determinism
    __syncthreads();
    if (t == 0) {
        __threadfence();
        int done = atomicAdd(&g_donectr, 1);
        if (done == NGEMM - 1) {
            atomicExch(&g_tilectr, 0);
            atomicExch(&g_donectr, 0);
        }
    }
#undef ISSUE
#undef CONSUME
}

// ================= 3) gather-axpy assembly with inline metadata ============
__global__ void __launch_bounds__(512) k_out(const float *__restrict__ bom,
                                             const float *__restrict__ bdcn,
                                             float *__restrict__ out) {
    __shared__ float4 smw[KKN][16];
    __shared__ int4 smi[KKN][16];
    __shared__ float st[16][257];
    int b = blockIdx.y;
    int p0 = blockIdx.x * 16;
    int t = threadIdx.x;

    if (t < KKN * 16) {
        int kk = t >> 4;
        int pl = t & 15;
        int p = p0 + pl;
        int oy = p >> 6, ox = p & 63;
        size_t ob = (size_t)b * 27 * HWP;
#define OMSUM(ch) (g_ompart[0][ob + (size_t)(ch) * HWP + p] + g_ompart[1][ob + (size_t)(ch) * HWP + p] + \
                   g_ompart[2][ob + (size_t)(ch) * HWP + p] + g_ompart[3][ob + (size_t)(ch) * HWP + p])
        float dy = OMSUM(kk) + bom[kk];
        float dx = OMSUM(9 + kk) + bom[9 + kk];
        float mz = OMSUM(18 + kk) + bom[18 + kk];
#undef OMSUM
        float m = 1.f / (1.f + expf(-mz));
        int ki = kk / 3, kj = kk % 3;
        float py = (float)(oy - 1 + ki) + dy;
        float px = (float)(ox - 1 + kj) + dx;
        float y0f = floorf(py), x0f = floorf(px);
        float ly = py - y0f, lx = px - x0f;
        int y0 = (int)y0f, x0 = (int)x0f;
        int y1 = y0 + 1, x1 = x0 + 1;

        float v00 = (y0 >= 0 && y0 < HH && x0 >= 0 && x0 < WW) ? 1.f : 0.f;
        float v01 = (y0 >= 0 && y0 < HH && x1 >= 0 && x1 < WW) ? 1.f : 0.f;
        float v10 = (y1 >= 0 && y1 < HH && x0 >= 0 && x0 < WW) ? 1.f : 0.f;
        float v11 = (y1 >= 0 && y1 < HH && x1 >= 0 && x1 < WW) ? 1.f : 0.f;
        int cy0 = min(max(y0, 0), HH - 1), cy1 = min(max(y1, 0), HH - 1);
        int cx0 = min(max(x0, 0), WW - 1), cx1 = min(max(x1, 0), WW - 1);

        smw[kk][pl] = make_float4((1.f - ly) * (1.f - lx) * m * v00,
                                  (1.f - ly) * lx * m * v01,
                                  ly * (1.f - lx) * m * v10,
                                  ly * lx * m * v11);
        smi[kk][pl] = make_int4((cy0 * WW + cx0) * COUT, (cy0 * WW + cx1) * COUT,
                                (cy1 * WW + cx0) * COUT, (cy1 * WW + cx1) * COUT);
    }
    __syncthreads();

    int pl = t >> 5;
    int ol = (t & 31) * 8;

    u64 a[4];
    {
        float4 b0 = *(const float4 *)(bdcn + ol);
        float4 b1 = *(const float4 *)(bdcn + ol + 4);
        a[0] = pack2(b0.x, b0.y); a[1] = pack2(b0.z, b0.w);
        a[2] = pack2(b1.x, b1.y); a[3] = pack2(b1.z, b1.w);
    }

#define CORNER(W, OFFS) do { \
        u64 ww = pack2((W), (W)); \
        uint4 v = __ldg((const uint4 *)(yk + (OFFS) + ol)); \
        const __half2 *hp = (const __half2 *)&v; \
        _Pragma("unroll") \
        for (int j = 0; j < 4; j++) { \
            float2 f = __half22float2(hp[j]); \
            a[j] = ffma2(pack2(f.x, f.y), ww, a[j]); \
        } \
    } while (0)

#pragma unroll 1
    for (int kk = 0; kk < KKN; kk++) {
        const __half *yk = g_y + (size_t)(kk * BB + b) * HWP * COUT;
        float4 w = smw[kk][pl];
        int4 ii = smi[kk][pl];
        CORNER(w.x, ii.x);
        CORNER(w.y, ii.y);
        CORNER(w.z, ii.z);
        CORNER(w.w, ii.w);
    }
#undef CORNER

    float *sr = &st[pl][ol];
#pragma unroll
    for (int j = 0; j < 4; j++) {
        float lo, hi; unpack2(a[j], lo, hi);
        sr[2 * j] = lo; sr[2 * j + 1] = hi;
    }
    __syncthreads();
    for (int idx = t; idx < 4096; idx += 512) {
        int o = idx >> 4, p2 = idx & 15;
        out[((size_t)b * COUT + o) * HWP + p0 + p2] = st[p2][o];
    }
}

// ---------------- launch ----------------
extern "C" void kernel_launch(void *const *d_in, const int *in_sizes, int n_in,
                              void *d_out, int out_size) {
    const float *x = (const float *)d_in[0];
    const float *w_om = (const float *)d_in[1];
    const float *b_om = (const float *)d_in[2];
    const float *w_dcn = (const float *)d_in[3];
    const float *b_dcn = (const float *)d_in[4];
    float *out = (float *)d_out;

    static int smem_set = 0;
    if (!smem_set) {
        cudaFuncSetAttribute(k_main, cudaFuncAttributeMaxDynamicSharedMemorySize, SM_TOT);
        smem_set = 1;
    }

    k_prep<<<NB_PREP, 256>>>(x, w_dcn);

    k_main<<<NB_OM + NGEMM, 256, SM_TOT>>>(x, w_om);

    k_out<<<dim3(HWP / 16, BB), 512>>>(b_om, b_dcn, out);
}

// round 10
// speedup vs baseline: 1.3048x; 1.3048x over previous
#include <cuda_runtime.h>
#include <cuda_fp16.h>
#include <math.h>
#include <stdint.h>

#define BB 8
#define CIN 256
#define COUT 256
#define HH 64
#define WW 64
#define HWP 4096
#define KKN 9

typedef unsigned long long u64;

// ---------------- low-level helpers ----------------
__device__ __forceinline__ u64 pack2(float lo, float hi) {
    u64 r; asm("mov.b64 %0, {%1,%2};" : "=l"(r) : "f"(lo), "f"(hi)); return r;
}
__device__ __forceinline__ void unpack2(u64 v, float &lo, float &hi) {
    asm("mov.b64 {%0,%1}, %2;" : "=f"(lo), "=f"(hi) : "l"(v));
}
__device__ __forceinline__ u64 ffma2(u64 a, u64 b, u64 c) {
    u64 d; asm("fma.rn.f32x2 %0, %1, %2, %3;" : "=l"(d) : "l"(a), "l"(b), "l"(c)); return d;
}
__device__ __forceinline__ uint32_t smem_u32(const void *p) {
    uint32_t a; asm("{ .reg .u64 t; cvta.to.shared.u64 t, %1; cvt.u32.u64 %0, t; }" : "=r"(a) : "l"(p));
    return a;
}

#define CP_ASYNC16(dst, src) \
    asm volatile("cp.async.cg.shared.global [%0], [%1], 16;" :: "r"(dst), "l"(src) : "memory")
#define CP_COMMIT() asm volatile("cp.async.commit_group;" ::: "memory")
#define CP_WAIT1() asm volatile("cp.async.wait_group 1;" ::: "memory")
#define CP_WAIT0() asm volatile("cp.async.wait_group 0;" ::: "memory")

#define LDSM_X4(r, addr) \
    asm volatile("ldmatrix.sync.aligned.m8n8.x4.shared.b16 {%0,%1,%2,%3}, [%4];" \
        : "=r"((r)[0]), "=r"((r)[1]), "=r"((r)[2]), "=r"((r)[3]) : "r"(addr))
#define LDSM_X2(r, addr) \
    asm volatile("ldmatrix.sync.aligned.m8n8.x2.shared.b16 {%0,%1}, [%2];" \
        : "=r"((r)[0]), "=r"((r)[1]) : "r"(addr))

#define MMA_FP16(d, a, b) \
    asm volatile("mma.sync.aligned.m16n8k16.row.col.f32.f16.f16.f32 " \
        "{%0,%1,%2,%3}, {%4,%5,%6,%7}, {%8,%9}, {%0,%1,%2,%3};" \
        : "+f"((d)[0]), "+f"((d)[1]), "+f"((d)[2]), "+f"((d)[3]) \
        : "r"((a)[0]), "r"((a)[1]), "r"((a)[2]), "r"((a)[3]), "r"((b)[0]), "r"((b)[1]))

#define SWZ(o) ((o) ^ (((o) >> 3) & 0x70))

// ---------------- scratch ----------------
__device__ __half g_xf[(size_t)BB * HWP * CIN];          // [b][p][c] fp16
__device__ __half g_wf[KKN * COUT * CIN];                // [kk][o][c] fp16
__device__ __half g_y[(size_t)KKN * BB * HWP * COUT];    // [kk][b][p][o] fp16
__device__ float  g_ompart[8][BB * 27 * HWP];            // 8 c-splits of 32

// ================= 1) unified prep: om-conv + transpose + wconv ============
#define NB_OM 256
#define NB_TR 8192
#define NB_WS 144
#define NB_PREP (NB_OM + NB_TR + NB_WS)

__global__ void __launch_bounds__(256) k_prep(const float *__restrict__ x,
                                              const float *__restrict__ wom,
                                              const float *__restrict__ wdcn) {
    __shared__ __align__(16) char psm[16 * 243 * 8];   // 31104 B
    int blk = blockIdx.x;
    int t = threadIdx.x;

    if (blk < NB_OM) {
        // -------- om conv: 27ch 3x3, 4 pixels/thread, c-split 8 ----------
        int split = blk & 7;
        int b = (blk >> 3) & 7;
        int rb = blk >> 6;            // 0..3, 16 rows each
        int s = t >> 6;
        int ox = t & 63;
        int y0 = rb * 16 + s * 4;

        u64 acc0[27], acc1[27];
#pragma unroll
        for (int i = 0; i < 27; i++) { acc0[i] = 0ULL; acc1[i] = 0ULL; }

        bool rowok[6]; int rowoff[6];
#pragma unroll
        for (int r = 0; r < 6; r++) {
            int y = y0 - 1 + r;
            rowok[r] = (y >= 0) && (y < HH);
            rowoff[r] = rowok[r] ? y * WW : 0;
        }
        bool colok[3]; int coloff[3];
#pragma unroll
        for (int c = 0; c < 3; c++) {
            int xx = ox - 1 + c;
            colok[c] = (xx >= 0) && (xx < WW);
            coloff[c] = colok[c] ? xx : 0;
        }

        int cbase = split * 32;
        const float *xb = x + (size_t)b * CIN * HWP;
        u64 *wshf = (u64 *)psm;

        for (int cc = 0; cc < 32; cc += 16) {
            __syncthreads();
            for (int j = t; j < 16 * 243; j += 256) {
                int oc = j / 144, rem = j % 144;
                float g = wom[(size_t)oc * 2304 + (size_t)(cbase + cc) * 9 + rem];
                wshf[(rem / 9) * 243 + oc * 9 + (rem % 9)] = pack2(g, g);
            }
            __syncthreads();
#pragma unroll 1
            for (int cil = 0; cil < 16; cil++) {
                const float *xc = xb + (size_t)(cbase + cc + cil) * HWP;
                float a[6][3];
#pragma unroll
                for (int r = 0; r < 6; r++)
#pragma unroll
                    for (int c = 0; c < 3; c++)
                        a[r][c] = (rowok[r] && colok[c]) ? __ldg(xc + rowoff[r] + coloff[c]) : 0.f;
                u64 pv0[9], pv1[9];
#pragma unroll
                for (int kk = 0; kk < 9; kk++) {
                    int ki = kk / 3, kj = kk % 3;
                    pv0[kk] = pack2(a[ki][kj], a[ki + 2][kj]);
                    pv1[kk] = pack2(a[ki + 1][kj], a[ki + 3][kj]);
                }
                const u64 *wrow = &wshf[cil * 243];
#pragma unroll
                for (int kk = 0; kk < 9; kk++)
#pragma unroll
                    for (int oc = 0; oc < 27; oc++) {
                        u64 w = wrow[oc * 9 + kk];
                        acc0[oc] = ffma2(pv0[kk], w, acc0[oc]);
                        acc1[oc] = ffma2(pv1[kk], w, acc1[oc]);
                    }
            }
        }

        float *dst = &g_ompart[split][(size_t)b * 27 * HWP];
#pragma unroll
        for (int oc = 0; oc < 27; oc++) {
            float l0, h0, l1, h1;
            unpack2(acc0[oc], l0, h0);
            unpack2(acc1[oc], l1, h1);
            size_t base = (size_t)oc * HWP + y0 * WW + ox;
            dst[base] = l0;
            dst[base + WW] = l1;
            dst[base + 2 * WW] = h0;
            dst[base + 3 * WW] = h1;
        }
    } else if (blk < NB_OM + NB_TR) {
        // -------- NCHW -> NHWC transpose, fp16 --------
        int n = blk - NB_OM;
        int p0 = (n & 127) * 32;
        int c0 = ((n >> 7) & 7) * 32;
        int b = n >> 10;
        float (*tile)[33] = (float (*)[33])psm;
        int tx = t & 31, ty = t >> 5;
        const float *src = x + (size_t)b * CIN * HWP;
#pragma unroll
        for (int k = 0; k < 32; k += 8)
            tile[ty + k][tx] = src[(size_t)(c0 + ty + k) * HWP + p0 + tx];
        __syncthreads();
        __half *dh = g_xf + (size_t)b * HWP * CIN;
#pragma unroll
        for (int k = 0; k < 32; k += 8)
            dh[(size_t)(p0 + ty + k) * CIN + c0 + tx] = __float2half_rn(tile[tx][ty + k]);
    } else {
        // -------- w_dcn -> [kk][o][c] fp16 --------
        int blkL = blk - (NB_OM + NB_TR);
        int base = blkL * 4096 + t;
#pragma unroll
        for (int k = 0; k < 16; k++) {
            int i = base + k * 256;
            int c = i % CIN;
            int o = (i / CIN) % COUT;
            int kk = i / (CIN * COUT);
            g_wf[i] = __float2half_rn(wdcn[(size_t)(o * CIN + c) * KKN + kk]);
        }
    }
}

// ================= 2) persistent dense GEMMs: EXACT R7 loop ============
#define NT 4608
#define NSMG 296
#define KC 64
#define STAGE_BYTES 32768
#define X_OFF 0
#define W_OFF 16384
#define SM_TOT (2 * STAGE_BYTES)

struct TileInfo {
    const __half *xf, *wf;
    size_t yoff;
};
__device__ __forceinline__ TileInfo tile_decode(int ti) {
    int inner = ti % 18;
    int outer = ti / 18;
    int b = outer >> 5;
    int p0 = (outer & 31) * 128;
    int kk = inner >> 1;
    int o0 = (inner & 1) * 128;
    TileInfo r;
    r.xf = g_xf + ((size_t)b * HWP + p0) * CIN;
    r.wf = g_wf + ((size_t)kk * COUT + o0) * CIN;
    r.yoff = (((size_t)(kk * BB + b) * HWP + p0) * COUT) + o0;
    return r;
}

__global__ void __launch_bounds__(256, 2) k_gemm() {
    extern __shared__ char smem[];
    uint32_t sb = smem_u32(smem);
    int tid = threadIdx.x;
    int wid = tid >> 5, lane = tid & 31;
    int bid = blockIdx.x;

    int ntiles = (NT - bid + NSMG - 1) / NSMG;
    int NC = ntiles * 4;

    int lsw4[4], lrow4[4], latom4[4];
#pragma unroll
    for (int k2 = 0; k2 < 4; k2++) {
        int idx = tid + k2 * 256;
        lrow4[k2] = idx >> 3;
        latom4[k2] = idx & 7;
        lsw4[k2] = SWZ((idx >> 3) * 128 + (idx & 7) * 16);
    }

#define ISSUE_CHUNK(n) do { \
        int _ti = bid + ((n) >> 2) * NSMG; \
        TileInfo _t = tile_decode(_ti); \
        int _c0 = ((n) & 3) * KC; \
        uint32_t _stb = sb + ((n) & 1) * STAGE_BYTES; \
        _Pragma("unroll") \
        for (int k2 = 0; k2 < 4; k2++) { \
            size_t g = (size_t)lrow4[k2] * CIN + _c0 + latom4[k2] * 8; \
            CP_ASYNC16(_stb + X_OFF + lsw4[k2], _t.xf + g); \
            CP_ASYNC16(_stb + W_OFF + lsw4[k2], _t.wf + g); \
        } \
    } while (0)

    int wp = wid >> 2;
    int wo = wid & 3;
    int abase = (wp * 64 + (lane & 15)) * 128 + ((lane >> 4) * 8) * 2;
    int bbase = (wo * 32 + (lane & 7)) * 128 + (((lane >> 3) & 1) * 8) * 2;

    float d[4][4][4];
#pragma unroll
    for (int mt = 0; mt < 4; mt++)
#pragma unroll
        for (int nt = 0; nt < 4; nt++)
#pragma unroll
            for (int j = 0; j < 4; j++) d[mt][nt][j] = 0.f;

    ISSUE_CHUNK(0); CP_COMMIT();
    if (NC > 1) ISSUE_CHUNK(1);
    CP_COMMIT();

    for (int n = 0; n < NC; n++) {
        if (n + 1 < NC) { CP_WAIT1(); } else { CP_WAIT0(); }
        __syncthreads();

        uint32_t stb = sb + (n & 1) * STAGE_BYTES;
#pragma unroll
        for (int ks = 0; ks < 4; ks++) {
            uint32_t ah[4][4];
#pragma unroll
            for (int mt = 0; mt < 4; mt++)
                LDSM_X4(ah[mt], stb + X_OFF + SWZ(abase + mt * 2048 + ks * 32));
            uint32_t bh[4][2];
#pragma unroll
            for (int nt = 0; nt < 4; nt++)
                LDSM_X2(bh[nt], stb + W_OFF + SWZ(bbase + nt * 1024 + ks * 32));
#pragma unroll
            for (int mt = 0; mt < 4; mt++)
#pragma unroll
                for (int nt = 0; nt < 4; nt++)
                    MMA_FP16(d[mt][nt], ah[mt], bh[nt]);
        }
        __syncthreads();

        if (n + 2 < NC) ISSUE_CHUNK(n + 2);
        CP_COMMIT();

        if ((n & 3) == 3) {
            int ti = bid + (n >> 2) * NSMG;
            TileInfo tinfo = tile_decode(ti);
            __half *yo = g_y + tinfo.yoff;
#pragma unroll
            for (int mt = 0; mt < 4; mt++) {
                int r0 = wp * 64 + mt * 16 + (lane >> 2);
#pragma unroll
                for (int nt = 0; nt < 4; nt++) {
                    int c = wo * 32 + nt * 8 + (lane & 3) * 2;
                    *(__half2 *)(yo + (size_t)r0 * COUT + c) = __floats2half2_rn(d[mt][nt][0], d[mt][nt][1]);
                    *(__half2 *)(yo + (size_t)(r0 + 8) * COUT + c) = __floats2half2_rn(d[mt][nt][2], d[mt][nt][3]);
                    d[mt][nt][0] = 0.f; d[mt][nt][1] = 0.f; d[mt][nt][2] = 0.f; d[mt][nt][3] = 0.f;
                }
            }
        }
    }
#undef ISSUE_CHUNK
}

// ================= 3) gather-axpy assembly with inline metadata ============
__global__ void __launch_bounds__(512) k_out(const float *__restrict__ bom,
                                             const float *__restrict__ bdcn,
                                             float *__restrict__ out) {
    __shared__ float4 smw[KKN][16];
    __shared__ int4 smi[KKN][16];
    __shared__ float st[16][257];
    int b = blockIdx.y;
    int p0 = blockIdx.x * 16;
    int t = threadIdx.x;

    if (t < KKN * 16) {
        int kk = t >> 4;
        int pl = t & 15;
        int p = p0 + pl;
        int oy = p >> 6, ox = p & 63;
        size_t ob = (size_t)b * 27 * HWP;
#define OMSUM(ch) (g_ompart[0][ob + (size_t)(ch) * HWP + p] + g_ompart[1][ob + (size_t)(ch) * HWP + p] + \
                   g_ompart[2][ob + (size_t)(ch) * HWP + p] + g_ompart[3][ob + (size_t)(ch) * HWP + p] + \
                   g_ompart[4][ob + (size_t)(ch) * HWP + p] + g_ompart[5][ob + (size_t)(ch) * HWP + p] + \
                   g_ompart[6][ob + (size_t)(ch) * HWP + p] + g_ompart[7][ob + (size_t)(ch) * HWP + p])
        float dy = OMSUM(kk) + bom[kk];
        float dx = OMSUM(9 + kk) + bom[9 + kk];
        float mz = OMSUM(18 + kk) + bom[18 + kk];
#undef OMSUM
        float m = 1.f / (1.f + expf(-mz));
        int ki = kk / 3, kj = kk % 3;
        float py = (float)(oy - 1 + ki) + dy;
        float px = (float)(ox - 1 + kj) + dx;
        float y0f = floorf(py), x0f = floorf(px);
        float ly = py - y0f, lx = px - x0f;
        int y0 = (int)y0f, x0 = (int)x0f;
        int y1 = y0 + 1, x1 = x0 + 1;

        float v00 = (y0 >= 0 && y0 < HH && x0 >= 0 && x0 < WW) ? 1.f : 0.f;
        float v01 = (y0 >= 0 && y0 < HH && x1 >= 0 && x1 < WW) ? 1.f : 0.f;
        float v10 = (y1 >= 0 && y1 < HH && x0 >= 0 && x0 < WW) ? 1.f : 0.f;
        float v11 = (y1 >= 0 && y1 < HH && x1 >= 0 && x1 < WW) ? 1.f : 0.f;
        int cy0 = min(max(y0, 0), HH - 1), cy1 = min(max(y1, 0), HH - 1);
        int cx0 = min(max(x0, 0), WW - 1), cx1 = min(max(x1, 0), WW - 1);

        smw[kk][pl] = make_float4((1.f - ly) * (1.f - lx) * m * v00,
                                  (1.f - ly) * lx * m * v01,
                                  ly * (1.f - lx) * m * v10,
                                  ly * lx * m * v11);
        smi[kk][pl] = make_int4((cy0 * WW + cx0) * COUT, (cy0 * WW + cx1) * COUT,
                                (cy1 * WW + cx0) * COUT, (cy1 * WW + cx1) * COUT);
    }
    __syncthreads();

    int pl = t >> 5;
    int ol = (t & 31) * 8;

    u64 a[4];
    {
        float4 b0 = *(const float4 *)(bdcn + ol);
        float4 b1 = *(const float4 *)(bdcn + ol + 4);
        a[0] = pack2(b0.x, b0.y); a[1] = pack2(b0.z, b0.w);
        a[2] = pack2(b1.x, b1.y); a[3] = pack2(b1.z, b1.w);
    }

#define CORNER(W, OFFS) do { \
        u64 ww = pack2((W), (W)); \
        uint4 v = __ldg((const uint4 *)(yk + (OFFS) + ol)); \
        const __half2 *hp = (const __half2 *)&v; \
        _Pragma("unroll") \
        for (int j = 0; j < 4; j++) { \
            float2 f = __half22float2(hp[j]); \
            a[j] = ffma2(pack2(f.x, f.y), ww, a[j]); \
        } \
    } while (0)

#pragma unroll 1
    for (int kk = 0; kk < KKN; kk++) {
        const __half *yk = g_y + (size_t)(kk * BB + b) * HWP * COUT;
        float4 w = smw[kk][pl];
        int4 ii = smi[kk][pl];
        CORNER(w.x, ii.x);
        CORNER(w.y, ii.y);
        CORNER(w.z, ii.z);
        CORNER(w.w, ii.w);
    }
#undef CORNER

    float *sr = &st[pl][ol];
#pragma unroll
    for (int j = 0; j < 4; j++) {
        float lo, hi; unpack2(a[j], lo, hi);
        sr[2 * j] = lo; sr[2 * j + 1] = hi;
    }
    __syncthreads();
    for (int idx = t; idx < 4096; idx += 512) {
        int o = idx >> 4, p2 = idx & 15;
        out[((size_t)b * COUT + o) * HWP + p0 + p2] = st[p2][o];
    }
}

// ---------------- launch ----------------
extern "C" void kernel_launch(void *const *d_in, const int *in_sizes, int n_in,
                              void *d_out, int out_size) {
    const float *x = (const float *)d_in[0];
    const float *w_om = (const float *)d_in[1];
    const float *b_om = (const float *)d_in[2];
    const float *w_dcn = (const float *)d_in[3];
    const float *b_dcn = (const float *)d_in[4];
    float *out = (float *)d_out;

    static int smem_set = 0;
    if (!smem_set) {
        cudaFuncSetAttribute(k_gemm, cudaFuncAttributeMaxDynamicSharedMemorySize, SM_TOT);
        smem_set = 1;
    }

    k_prep<<<NB_PREP, 256>>>(x, w_om, w_dcn);

    k_gemm<<<NSMG, 256, SM_TOT>>>();

    k_out<<<dim3(HWP / 16, BB), 512>>>(b_om, b_dcn, out);
}

// round 11
// speedup vs baseline: 1.3870x; 1.0630x over previous
#include <cuda_runtime.h>
#include <cuda_fp16.h>
#include <math.h>
#include <stdint.h>

#define BB 8
#define CIN 256
#define COUT 256
#define HH 64
#define WW 64
#define HWP 4096
#define KKN 9

typedef unsigned long long u64;

// ---------------- low-level helpers ----------------
__device__ __forceinline__ u64 pack2(float lo, float hi) {
    u64 r; asm("mov.b64 %0, {%1,%2};" : "=l"(r) : "f"(lo), "f"(hi)); return r;
}
__device__ __forceinline__ void unpack2(u64 v, float &lo, float &hi) {
    asm("mov.b64 {%0,%1}, %2;" : "=f"(lo), "=f"(hi) : "l"(v));
}
__device__ __forceinline__ u64 ffma2(u64 a, u64 b, u64 c) {
    u64 d; asm("fma.rn.f32x2 %0, %1, %2, %3;" : "=l"(d) : "l"(a), "l"(b), "l"(c)); return d;
}
__device__ __forceinline__ uint32_t smem_u32(const void *p) {
    uint32_t a; asm("{ .reg .u64 t; cvta.to.shared.u64 t, %1; cvt.u32.u64 %0, t; }" : "=r"(a) : "l"(p));
    return a;
}

#define CP_ASYNC16(dst, src) \
    asm volatile("cp.async.cg.shared.global [%0], [%1], 16;" :: "r"(dst), "l"(src) : "memory")
#define CP_COMMIT() asm volatile("cp.async.commit_group;" ::: "memory")
#define CP_WAIT1() asm volatile("cp.async.wait_group 1;" ::: "memory")
#define CP_WAIT0() asm volatile("cp.async.wait_group 0;" ::: "memory")

#define LDSM_X4(r, addr) \
    asm volatile("ldmatrix.sync.aligned.m8n8.x4.shared.b16 {%0,%1,%2,%3}, [%4];" \
        : "=r"((r)[0]), "=r"((r)[1]), "=r"((r)[2]), "=r"((r)[3]) : "r"(addr))
#define LDSM_X2(r, addr) \
    asm volatile("ldmatrix.sync.aligned.m8n8.x2.shared.b16 {%0,%1}, [%2];" \
        : "=r"((r)[0]), "=r"((r)[1]) : "r"(addr))

#define MMA_FP16(d, a, b) \
    asm volatile("mma.sync.aligned.m16n8k16.row.col.f32.f16.f16.f32 " \
        "{%0,%1,%2,%3}, {%4,%5,%6,%7}, {%8,%9}, {%0,%1,%2,%3};" \
        : "+f"((d)[0]), "+f"((d)[1]), "+f"((d)[2]), "+f"((d)[3]) \
        : "r"((a)[0]), "r"((a)[1]), "r"((a)[2]), "r"((a)[3]), "r"((b)[0]), "r"((b)[1]))

#define SWZ(o) ((o) ^ (((o) >> 3) & 0x70))

// ---------------- scratch ----------------
__device__ __half g_xf[(size_t)BB * HWP * CIN];          // [b][p][c] fp16
__device__ __half g_wf[KKN * COUT * CIN];                // [kk][o][c] fp16
__device__ __half g_y[(size_t)KKN * BB * HWP * COUT];    // [kk][b][p][o] fp16
__device__ float  g_ompart[8][BB * 27 * HWP];            // 8 c-splits of 32

// ================= 1a) om conv: 27ch 3x3, 4 pixels/thread, c-split 8 ============
#define NB_OM 256

__global__ void __launch_bounds__(256) k_om(const float *__restrict__ x,
                                            const float *__restrict__ wom) {
    __shared__ __align__(16) u64 wshf[16 * 243];
    int blk = blockIdx.x;
    int t = threadIdx.x;

    int split = blk & 7;
    int b = (blk >> 3) & 7;
    int rb = blk >> 6;            // 0..3, 16 rows each
    int s = t >> 6;
    int ox = t & 63;
    int y0 = rb * 16 + s * 4;

    u64 acc0[27], acc1[27];
#pragma unroll
    for (int i = 0; i < 27; i++) { acc0[i] = 0ULL; acc1[i] = 0ULL; }

    bool rowok[6]; int rowoff[6];
#pragma unroll
    for (int r = 0; r < 6; r++) {
        int y = y0 - 1 + r;
        rowok[r] = (y >= 0) && (y < HH);
        rowoff[r] = rowok[r] ? y * WW : 0;
    }
    bool colok[3]; int coloff[3];
#pragma unroll
    for (int c = 0; c < 3; c++) {
        int xx = ox - 1 + c;
        colok[c] = (xx >= 0) && (xx < WW);
        coloff[c] = colok[c] ? xx : 0;
    }

    int cbase = split * 32;
    const float *xb = x + (size_t)b * CIN * HWP;

    for (int cc = 0; cc < 32; cc += 16) {
        __syncthreads();
        for (int j = t; j < 16 * 243; j += 256) {
            int oc = j / 144, rem = j % 144;
            float g = wom[(size_t)oc * 2304 + (size_t)(cbase + cc) * 9 + rem];
            wshf[(rem / 9) * 243 + oc * 9 + (rem % 9)] = pack2(g, g);
        }
        __syncthreads();
#pragma unroll 1
        for (int cil = 0; cil < 16; cil++) {
            const float *xc = xb + (size_t)(cbase + cc + cil) * HWP;
            float a[6][3];
#pragma unroll
            for (int r = 0; r < 6; r++)
#pragma unroll
                for (int c = 0; c < 3; c++)
                    a[r][c] = (rowok[r] && colok[c]) ? __ldg(xc + rowoff[r] + coloff[c]) : 0.f;
            u64 pv0[9], pv1[9];
#pragma unroll
            for (int kk = 0; kk < 9; kk++) {
                int ki = kk / 3, kj = kk % 3;
                pv0[kk] = pack2(a[ki][kj], a[ki + 2][kj]);
                pv1[kk] = pack2(a[ki + 1][kj], a[ki + 3][kj]);
            }
            const u64 *wrow = &wshf[cil * 243];
#pragma unroll
            for (int kk = 0; kk < 9; kk++)
#pragma unroll
                for (int oc = 0; oc < 27; oc++) {
                    u64 w = wrow[oc * 9 + kk];
                    acc0[oc] = ffma2(pv0[kk], w, acc0[oc]);
                    acc1[oc] = ffma2(pv1[kk], w, acc1[oc]);
                }
        }
    }

    float *dst = &g_ompart[split][(size_t)b * 27 * HWP];
#pragma unroll
    for (int oc = 0; oc < 27; oc++) {
        float l0, h0, l1, h1;
        unpack2(acc0[oc], l0, h0);
        unpack2(acc1[oc], l1, h1);
        size_t base = (size_t)oc * HWP + y0 * WW + ox;
        dst[base] = l0;
        dst[base + WW] = l1;
        dst[base + 2 * WW] = h0;
        dst[base + 3 * WW] = h1;
    }
}

// ================= 1b) prep: transpose + w conversion (low-reg) ============
#define NB_TR 8192
#define NB_WS 144
#define NB_PREP (NB_TR + NB_WS)

__global__ void __launch_bounds__(256) k_prep(const float *__restrict__ x,
                                              const float *__restrict__ wdcn) {
    __shared__ float tile[32][33];
    int blk = blockIdx.x;
    int t = threadIdx.x;

    if (blk < NB_TR) {
        int p0 = (blk & 127) * 32;
        int c0 = ((blk >> 7) & 7) * 32;
        int b = blk >> 10;
        int tx = t & 31, ty = t >> 5;
        const float *src = x + (size_t)b * CIN * HWP;
#pragma unroll
        for (int k = 0; k < 32; k += 8)
            tile[ty + k][tx] = src[(size_t)(c0 + ty + k) * HWP + p0 + tx];
        __syncthreads();
        __half *dh = g_xf + (size_t)b * HWP * CIN;
#pragma unroll
        for (int k = 0; k < 32; k += 8)
            dh[(size_t)(p0 + ty + k) * CIN + c0 + tx] = __float2half_rn(tile[tx][ty + k]);
    } else {
        int blkL = blk - NB_TR;
        int base = blkL * 4096 + t;
#pragma unroll
        for (int k = 0; k < 16; k++) {
            int i = base + k * 256;
            int c = i % CIN;
            int o = (i / CIN) % COUT;
            int kk = i / (CIN * COUT);
            g_wf[i] = __float2half_rn(wdcn[(size_t)(o * CIN + c) * KKN + kk]);
        }
    }
}

// ================= 2) persistent dense GEMMs: EXACT R7 loop ============
#define NT 4608
#define NSMG 296
#define KC 64
#define STAGE_BYTES 32768
#define X_OFF 0
#define W_OFF 16384
#define SM_TOT (2 * STAGE_BYTES)

struct TileInfo {
    const __half *xf, *wf;
    size_t yoff;
};
__device__ __forceinline__ TileInfo tile_decode(int ti) {
    int inner = ti % 18;
    int outer = ti / 18;
    int b = outer >> 5;
    int p0 = (outer & 31) * 128;
    int kk = inner >> 1;
    int o0 = (inner & 1) * 128;
    TileInfo r;
    r.xf = g_xf + ((size_t)b * HWP + p0) * CIN;
    r.wf = g_wf + ((size_t)kk * COUT + o0) * CIN;
    r.yoff = (((size_t)(kk * BB + b) * HWP + p0) * COUT) + o0;
    return r;
}

__global__ void __launch_bounds__(256, 2) k_gemm() {
    extern __shared__ char smem[];
    uint32_t sb = smem_u32(smem);
    int tid = threadIdx.x;
    int wid = tid >> 5, lane = tid & 31;
    int bid = blockIdx.x;

    int ntiles = (NT - bid + NSMG - 1) / NSMG;
    int NC = ntiles * 4;

    int lsw4[4], lrow4[4], latom4[4];
#pragma unroll
    for (int k2 = 0; k2 < 4; k2++) {
        int idx = tid + k2 * 256;
        lrow4[k2] = idx >> 3;
        latom4[k2] = idx & 7;
        lsw4[k2] = SWZ((idx >> 3) * 128 + (idx & 7) * 16);
    }

#define ISSUE_CHUNK(n) do { \
        int _ti = bid + ((n) >> 2) * NSMG; \
        TileInfo _t = tile_decode(_ti); \
        int _c0 = ((n) & 3) * KC; \
        uint32_t _stb = sb + ((n) & 1) * STAGE_BYTES; \
        _Pragma("unroll") \
        for (int k2 = 0; k2 < 4; k2++) { \
            size_t g = (size_t)lrow4[k2] * CIN + _c0 + latom4[k2] * 8; \
            CP_ASYNC16(_stb + X_OFF + lsw4[k2], _t.xf + g); \
            CP_ASYNC16(_stb + W_OFF + lsw4[k2], _t.wf + g); \
        } \
    } while (0)

    int wp = wid >> 2;
    int wo = wid & 3;
    int abase = (wp * 64 + (lane & 15)) * 128 + ((lane >> 4) * 8) * 2;
    int bbase = (wo * 32 + (lane & 7)) * 128 + (((lane >> 3) & 1) * 8) * 2;

    float d[4][4][4];
#pragma unroll
    for (int mt = 0; mt < 4; mt++)
#pragma unroll
        for (int nt = 0; nt < 4; nt++)
#pragma unroll
            for (int j = 0; j < 4; j++) d[mt][nt][j] = 0.f;

    ISSUE_CHUNK(0); CP_COMMIT();
    if (NC > 1) ISSUE_CHUNK(1);
    CP_COMMIT();

    for (int n = 0; n < NC; n++) {
        if (n + 1 < NC) { CP_WAIT1(); } else { CP_WAIT0(); }
        __syncthreads();

        uint32_t stb = sb + (n & 1) * STAGE_BYTES;
#pragma unroll
        for (int ks = 0; ks < 4; ks++) {
            uint32_t ah[4][4];
#pragma unroll
            for (int mt = 0; mt < 4; mt++)
                LDSM_X4(ah[mt], stb + X_OFF + SWZ(abase + mt * 2048 + ks * 32));
            uint32_t bh[4][2];
#pragma unroll
            for (int nt = 0; nt < 4; nt++)
                LDSM_X2(bh[nt], stb + W_OFF + SWZ(bbase + nt * 1024 + ks * 32));
#pragma unroll
            for (int mt = 0; mt < 4; mt++)
#pragma unroll
                for (int nt = 0; nt < 4; nt++)
                    MMA_FP16(d[mt][nt], ah[mt], bh[nt]);
        }
        __syncthreads();

        if (n + 2 < NC) ISSUE_CHUNK(n + 2);
        CP_COMMIT();

        if ((n & 3) == 3) {
            int ti = bid + (n >> 2) * NSMG;
            TileInfo tinfo = tile_decode(ti);
            __half *yo = g_y + tinfo.yoff;
#pragma unroll
            for (int mt = 0; mt < 4; mt++) {
                int r0 = wp * 64 + mt * 16 + (lane >> 2);
#pragma unroll
                for (int nt = 0; nt < 4; nt++) {
                    int c = wo * 32 + nt * 8 + (lane & 3) * 2;
                    *(__half2 *)(yo + (size_t)r0 * COUT + c) = __floats2half2_rn(d[mt][nt][0], d[mt][nt][1]);
                    *(__half2 *)(yo + (size_t)(r0 + 8) * COUT + c) = __floats2half2_rn(d[mt][nt][2], d[mt][nt][3]);
                    d[mt][nt][0] = 0.f; d[mt][nt][1] = 0.f; d[mt][nt][2] = 0.f; d[mt][nt][3] = 0.f;
                }
            }
        }
    }
#undef ISSUE_CHUNK
}

// ================= 3) gather-axpy assembly with inline metadata ============
__global__ void __launch_bounds__(512) k_out(const float *__restrict__ bom,
                                             const float *__restrict__ bdcn,
                                             float *__restrict__ out) {
    __shared__ float4 smw[KKN][16];
    __shared__ int4 smi[KKN][16];
    __shared__ float st[16][257];
    int b = blockIdx.y;
    int p0 = blockIdx.x * 16;
    int t = threadIdx.x;

    if (t < KKN * 16) {
        int kk = t >> 4;
        int pl = t & 15;
        int p = p0 + pl;
        int oy = p >> 6, ox = p & 63;
        size_t ob = (size_t)b * 27 * HWP;
#define OMSUM(ch) (g_ompart[0][ob + (size_t)(ch) * HWP + p] + g_ompart[1][ob + (size_t)(ch) * HWP + p] + \
                   g_ompart[2][ob + (size_t)(ch) * HWP + p] + g_ompart[3][ob + (size_t)(ch) * HWP + p] + \
                   g_ompart[4][ob + (size_t)(ch) * HWP + p] + g_ompart[5][ob + (size_t)(ch) * HWP + p] + \
                   g_ompart[6][ob + (size_t)(ch) * HWP + p] + g_ompart[7][ob + (size_t)(ch) * HWP + p])
        float dy = OMSUM(kk) + bom[kk];
        float dx = OMSUM(9 + kk) + bom[9 + kk];
        float mz = OMSUM(18 + kk) + bom[18 + kk];
#undef OMSUM
        float m = 1.f / (1.f + expf(-mz));
        int ki = kk / 3, kj = kk % 3;
        float py = (float)(oy - 1 + ki) + dy;
        float px = (float)(ox - 1 + kj) + dx;
        float y0f = floorf(py), x0f = floorf(px);
        float ly = py - y0f, lx = px - x0f;
        int y0 = (int)y0f, x0 = (int)x0f;
        int y1 = y0 + 1, x1 = x0 + 1;

        float v00 = (y0 >= 0 && y0 < HH && x0 >= 0 && x0 < WW) ? 1.f : 0.f;
        float v01 = (y0 >= 0 && y0 < HH && x1 >= 0 && x1 < WW) ? 1.f : 0.f;
        float v10 = (y1 >= 0 && y1 < HH && x0 >= 0 && x0 < WW) ? 1.f : 0.f;
        float v11 = (y1 >= 0 && y1 < HH && x1 >= 0 && x1 < WW) ? 1.f : 0.f;
        int cy0 = min(max(y0, 0), HH - 1), cy1 = min(max(y1, 0), HH - 1);
        int cx0 = min(max(x0, 0), WW - 1), cx1 = min(max(x1, 0), WW - 1);

        smw[kk][pl] = make_float4((1.f - ly) * (1.f - lx) * m * v00,
                                  (1.f - ly) * lx * m * v01,
                                  ly * (1.f - lx) * m * v10,
                                  ly * lx * m * v11);
        smi[kk][pl] = make_int4((cy0 * WW + cx0) * COUT, (cy0 * WW + cx1) * COUT,
                                (cy1 * WW + cx0) * COUT, (cy1 * WW + cx1) * COUT);
    }
    __syncthreads();

    int pl = t >> 5;
    int ol = (t & 31) * 8;

    u64 a[4];
    {
        float4 b0 = *(const float4 *)(bdcn + ol);
        float4 b1 = *(const float4 *)(bdcn + ol + 4);
        a[0] = pack2(b0.x, b0.y); a[1] = pack2(b0.z, b0.w);
        a[2] = pack2(b1.x, b1.y); a[3] = pack2(b1.z, b1.w);
    }

#define CORNER(W, OFFS) do { \
        u64 ww = pack2((W), (W)); \
        uint4 v = __ldg((const uint4 *)(yk + (OFFS) + ol)); \
        const __half2 *hp = (const __half2 *)&v; \
        _Pragma("unroll") \
        for (int j = 0; j < 4; j++) { \
            float2 f = __half22float2(hp[j]); \
            a[j] = ffma2(pack2(f.x, f.y), ww, a[j]); \
        } \
    } while (0)

#pragma unroll 1
    for (int kk = 0; kk < KKN; kk++) {
        const __half *yk = g_y + (size_t)(kk * BB + b) * HWP * COUT;
        float4 w = smw[kk][pl];
        int4 ii = smi[kk][pl];
        CORNER(w.x, ii.x);
        CORNER(w.y, ii.y);
        CORNER(w.z, ii.z);
        CORNER(w.w, ii.w);
    }
#undef CORNER

    float *sr = &st[pl][ol];
#pragma unroll
    for (int j = 0; j < 4; j++) {
        float lo, hi; unpack2(a[j], lo, hi);
        sr[2 * j] = lo; sr[2 * j + 1] = hi;
    }
    __syncthreads();
    for (int idx = t; idx < 4096; idx += 512) {
        int o = idx >> 4, p2 = idx & 15;
        out[((size_t)b * COUT + o) * HWP + p0 + p2] = st[p2][o];
    }
}

// ---------------- launch ----------------
extern "C" void kernel_launch(void *const *d_in, const int *in_sizes, int n_in,
                              void *d_out, int out_size) {
    const float *x = (const float *)d_in[0];
    const float *w_om = (const float *)d_in[1];
    const float *b_om = (const float *)d_in[2];
    const float *w_dcn = (const float *)d_in[3];
    const float *b_dcn = (const float *)d_in[4];
    float *out = (float *)d_out;

    static int smem_set = 0;
    if (!smem_set) {
        cudaFuncSetAttribute(k_gemm, cudaFuncAttributeMaxDynamicSharedMemorySize, SM_TOT);
        smem_set = 1;
    }

    k_prep<<<NB_PREP, 256>>>(x, w_dcn);

    k_om<<<NB_OM, 256>>>(x, w_om);

    k_gemm<<<NSMG, 256, SM_TOT>>>();

    k_out<<<dim3(HWP / 16, BB), 512>>>(b_om, b_dcn, out);
}

// round 12
// speedup vs baseline: 1.3873x; 1.0003x over previous
#include <cuda_runtime.h>
#include <cuda_fp16.h>
#include <math.h>
#include <stdint.h>

#define BB 8
#define CIN 256
#define COUT 256
#define HH 64
#define WW 64
#define HWP 4096
#define KKN 9

typedef unsigned long long u64;

// ---------------- low-level helpers ----------------
__device__ __forceinline__ u64 pack2(float lo, float hi) {
    u64 r; asm("mov.b64 %0, {%1,%2};" : "=l"(r) : "f"(lo), "f"(hi)); return r;
}
__device__ __forceinline__ void unpack2(u64 v, float &lo, float &hi) {
    asm("mov.b64 {%0,%1}, %2;" : "=f"(lo), "=f"(hi) : "l"(v));
}
__device__ __forceinline__ u64 ffma2(u64 a, u64 b, u64 c) {
    u64 d; asm("fma.rn.f32x2 %0, %1, %2, %3;" : "=l"(d) : "l"(a), "l"(b), "l"(c)); return d;
}
__device__ __forceinline__ uint32_t smem_u32(const void *p) {
    uint32_t a; asm("{ .reg .u64 t; cvta.to.shared.u64 t, %1; cvt.u32.u64 %0, t; }" : "=r"(a) : "l"(p));
    return a;
}

#define CP_ASYNC16(dst, src) \
    asm volatile("cp.async.cg.shared.global [%0], [%1], 16;" :: "r"(dst), "l"(src) : "memory")
#define CP_COMMIT() asm volatile("cp.async.commit_group;" ::: "memory")
#define CP_WAIT2() asm volatile("cp.async.wait_group 2;" ::: "memory")

#define LDSM_X4(r, addr) \
    asm volatile("ldmatrix.sync.aligned.m8n8.x4.shared.b16 {%0,%1,%2,%3}, [%4];" \
        : "=r"((r)[0]), "=r"((r)[1]), "=r"((r)[2]), "=r"((r)[3]) : "r"(addr))
#define LDSM_X2(r, addr) \
    asm volatile("ldmatrix.sync.aligned.m8n8.x2.shared.b16 {%0,%1}, [%2];" \
        : "=r"((r)[0]), "=r"((r)[1]) : "r"(addr))

#define MMA_FP16(d, a, b) \
    asm volatile("mma.sync.aligned.m16n8k16.row.col.f32.f16.f16.f32 " \
        "{%0,%1,%2,%3}, {%4,%5,%6,%7}, {%8,%9}, {%0,%1,%2,%3};" \
        : "+f"((d)[0]), "+f"((d)[1]), "+f"((d)[2]), "+f"((d)[3]) \
        : "r"((a)[0]), "r"((a)[1]), "r"((a)[2]), "r"((a)[3]), "r"((b)[0]), "r"((b)[1]))

#define SWZ(o) ((o) ^ (((o) >> 3) & 0x70))

// ---------------- scratch ----------------
__device__ __half g_xf[(size_t)BB * HWP * CIN];          // [b][p][c] fp16
__device__ __half g_wf[KKN * COUT * CIN];                // [kk][o][c] fp16
__device__ __half g_y[(size_t)KKN * BB * HWP * COUT];    // [kk][b][p][o] fp16
__device__ float  g_ompart[8][BB * 27 * HWP];            // 8 c-splits of 32

// ================= 1a) om conv: 27ch 3x3, 4 pixels/thread, c-split 8 ============
#define NB_OM 256

__global__ void __launch_bounds__(256) k_om(const float *__restrict__ x,
                                            const float *__restrict__ wom) {
    __shared__ __align__(16) u64 wshf[16 * 243];
    int blk = blockIdx.x;
    int t = threadIdx.x;

    int split = blk & 7;
    int b = (blk >> 3) & 7;
    int rb = blk >> 6;            // 0..3, 16 rows each
    int s = t >> 6;
    int ox = t & 63;
    int y0 = rb * 16 + s * 4;

    u64 acc0[27], acc1[27];
#pragma unroll
    for (int i = 0; i < 27; i++) { acc0[i] = 0ULL; acc1[i] = 0ULL; }

    bool rowok[6]; int rowoff[6];
#pragma unroll
    for (int r = 0; r < 6; r++) {
        int y = y0 - 1 + r;
        rowok[r] = (y >= 0) && (y < HH);
        rowoff[r] = rowok[r] ? y * WW : 0;
    }
    bool colok[3]; int coloff[3];
#pragma unroll
    for (int c = 0; c < 3; c++) {
        int xx = ox - 1 + c;
        colok[c] = (xx >= 0) && (xx < WW);
        coloff[c] = colok[c] ? xx : 0;
    }

    int cbase = split * 32;
    const float *xb = x + (size_t)b * CIN * HWP;

    for (int cc = 0; cc < 32; cc += 16) {
        __syncthreads();
        for (int j = t; j < 16 * 243; j += 256) {
            int oc = j / 144, rem = j % 144;
            float g = wom[(size_t)oc * 2304 + (size_t)(cbase + cc) * 9 + rem];
            wshf[(rem / 9) * 243 + oc * 9 + (rem % 9)] = pack2(g, g);
        }
        __syncthreads();
#pragma unroll 1
        for (int cil = 0; cil < 16; cil++) {
            const float *xc = xb + (size_t)(cbase + cc + cil) * HWP;
            float a[6][3];
#pragma unroll
            for (int r = 0; r < 6; r++)
#pragma unroll
                for (int c = 0; c < 3; c++)
                    a[r][c] = (rowok[r] && colok[c]) ? __ldg(xc + rowoff[r] + coloff[c]) : 0.f;
            u64 pv0[9], pv1[9];
#pragma unroll
            for (int kk = 0; kk < 9; kk++) {
                int ki = kk / 3, kj = kk % 3;
                pv0[kk] = pack2(a[ki][kj], a[ki + 2][kj]);
                pv1[kk] = pack2(a[ki + 1][kj], a[ki + 3][kj]);
            }
            const u64 *wrow = &wshf[cil * 243];
#pragma unroll
            for (int kk = 0; kk < 9; kk++)
#pragma unroll
                for (int oc = 0; oc < 27; oc++) {
                    u64 w = wrow[oc * 9 + kk];
                    acc0[oc] = ffma2(pv0[kk], w, acc0[oc]);
                    acc1[oc] = ffma2(pv1[kk], w, acc1[oc]);
                }
        }
    }

    float *dst = &g_ompart[split][(size_t)b * 27 * HWP];
#pragma unroll
    for (int oc = 0; oc < 27; oc++) {
        float l0, h0, l1, h1;
        unpack2(acc0[oc], l0, h0);
        unpack2(acc1[oc], l1, h1);
        size_t base = (size_t)oc * HWP + y0 * WW + ox;
        dst[base] = l0;
        dst[base + WW] = l1;
        dst[base + 2 * WW] = h0;
        dst[base + 3 * WW] = h1;
    }
}

// ================= 1b) prep: transpose + w conversion (low-reg) ============
#define NB_TR 8192
#define NB_WS 144
#define NB_PREP (NB_TR + NB_WS)

__global__ void __launch_bounds__(256) k_prep(const float *__restrict__ x,
                                              const float *__restrict__ wdcn) {
    __shared__ float tile[32][33];
    int blk = blockIdx.x;
    int t = threadIdx.x;

    if (blk < NB_TR) {
        int p0 = (blk & 127) * 32;
        int c0 = ((blk >> 7) & 7) * 32;
        int b = blk >> 10;
        int tx = t & 31, ty = t >> 5;
        const float *src = x + (size_t)b * CIN * HWP;
#pragma unroll
        for (int k = 0; k < 32; k += 8)
            tile[ty + k][tx] = src[(size_t)(c0 + ty + k) * HWP + p0 + tx];
        __syncthreads();
        __half *dh = g_xf + (size_t)b * HWP * CIN;
#pragma unroll
        for (int k = 0; k < 32; k += 8)
            dh[(size_t)(p0 + ty + k) * CIN + c0 + tx] = __float2half_rn(tile[tx][ty + k]);
    } else {
        int blkL = blk - NB_TR;
        int base = blkL * 4096 + t;
#pragma unroll
        for (int k = 0; k < 16; k++) {
            int i = base + k * 256;
            int c = i % CIN;
            int o = (i / CIN) % COUT;
            int kk = i / (CIN * COUT);
            g_wf[i] = __float2half_rn(wdcn[(size_t)(o * CIN + c) * KKN + kk]);
        }
    }
}

// ================= 2) persistent dense GEMMs: 3-stage cp.async ring ============
#define NT 4608
#define NSMG 296
#define KC 64
#define STAGE_BYTES 32768
#define X_OFF 0
#define W_OFF 16384
#define SM_TOT (3 * STAGE_BYTES)

struct TileInfo {
    const __half *xf, *wf;
    size_t yoff;
};
__device__ __forceinline__ TileInfo tile_decode(int ti) {
    int inner = ti % 18;
    int outer = ti / 18;
    int b = outer >> 5;
    int p0 = (outer & 31) * 128;
    int kk = inner >> 1;
    int o0 = (inner & 1) * 128;
    TileInfo r;
    r.xf = g_xf + ((size_t)b * HWP + p0) * CIN;
    r.wf = g_wf + ((size_t)kk * COUT + o0) * CIN;
    r.yoff = (((size_t)(kk * BB + b) * HWP + p0) * COUT) + o0;
    return r;
}

__global__ void __launch_bounds__(256, 2) k_gemm() {
    extern __shared__ char smem[];
    uint32_t sb = smem_u32(smem);
    int tid = threadIdx.x;
    int wid = tid >> 5, lane = tid & 31;
    int bid = blockIdx.x;

    int ntiles = (NT - bid + NSMG - 1) / NSMG;
    int NC = ntiles * 4;

    int lsw4[4], lrow4[4], latom4[4];
#pragma unroll
    for (int k2 = 0; k2 < 4; k2++) {
        int idx = tid + k2 * 256;
        lrow4[k2] = idx >> 3;
        latom4[k2] = idx & 7;
        lsw4[k2] = SWZ((idx >> 3) * 128 + (idx & 7) * 16);
    }

    // stage for chunk n = n % 3
#define ISSUE_CHUNK(n) do { \
        int _ti = bid + ((n) >> 2) * NSMG; \
        TileInfo _t = tile_decode(_ti); \
        int _c0 = ((n) & 3) * KC; \
        uint32_t _stb = sb + ((n) % 3) * STAGE_BYTES; \
        _Pragma("unroll") \
        for (int k2 = 0; k2 < 4; k2++) { \
            size_t g = (size_t)lrow4[k2] * CIN + _c0 + latom4[k2] * 8; \
            CP_ASYNC16(_stb + X_OFF + lsw4[k2], _t.xf + g); \
            CP_ASYNC16(_stb + W_OFF + lsw4[k2], _t.wf + g); \
        } \
    } while (0)

    int wp = wid >> 2;
    int wo = wid & 3;
    int abase = (wp * 64 + (lane & 15)) * 128 + ((lane >> 4) * 8) * 2;
    int bbase = (wo * 32 + (lane & 7)) * 128 + (((lane >> 3) & 1) * 8) * 2;

    float d[4][4][4];
#pragma unroll
    for (int mt = 0; mt < 4; mt++)
#pragma unroll
        for (int nt = 0; nt < 4; nt++)
#pragma unroll
            for (int j = 0; j < 4; j++) d[mt][nt][j] = 0.f;

    // prologue: 3 chunks in flight (NC >= 60 always for this problem size)
    ISSUE_CHUNK(0); CP_COMMIT();
    ISSUE_CHUNK(1); CP_COMMIT();
    ISSUE_CHUNK(2); CP_COMMIT();

    for (int n = 0; n < NC; n++) {
        // commits: 3 + n so far; chunk n has exactly 2 newer groups (some empty)
        CP_WAIT2();
        __syncthreads();

        uint32_t stb = sb + (n % 3) * STAGE_BYTES;
#pragma unroll
        for (int ks = 0; ks < 4; ks++) {
            uint32_t ah[4][4];
#pragma unroll
            for (int mt = 0; mt < 4; mt++)
                LDSM_X4(ah[mt], stb + X_OFF + SWZ(abase + mt * 2048 + ks * 32));
            uint32_t bh[4][2];
#pragma unroll
            for (int nt = 0; nt < 4; nt++)
                LDSM_X2(bh[nt], stb + W_OFF + SWZ(bbase + nt * 1024 + ks * 32));
#pragma unroll
            for (int mt = 0; mt < 4; mt++)
#pragma unroll
                for (int nt = 0; nt < 4; nt++)
                    MMA_FP16(d[mt][nt], ah[mt], bh[nt]);
        }
        __syncthreads();   // all warps done reading stage n%3 before overwrite

        if (n + 3 < NC) ISSUE_CHUNK(n + 3);
        CP_COMMIT();       // always commit (possibly empty) to keep group count aligned

        if ((n & 3) == 3) {
            int ti = bid + (n >> 2) * NSMG;
            TileInfo tinfo = tile_decode(ti);
            __half *yo = g_y + tinfo.yoff;
#pragma unroll
            for (int mt = 0; mt < 4; mt++) {
                int r0 = wp * 64 + mt * 16 + (lane >> 2);
#pragma unroll
                for (int nt = 0; nt < 4; nt++) {
                    int c = wo * 32 + nt * 8 + (lane & 3) * 2;
                    *(__half2 *)(yo + (size_t)r0 * COUT + c) = __floats2half2_rn(d[mt][nt][0], d[mt][nt][1]);
                    *(__half2 *)(yo + (size_t)(r0 + 8) * COUT + c) = __floats2half2_rn(d[mt][nt][2], d[mt][nt][3]);
                    d[mt][nt][0] = 0.f; d[mt][nt][1] = 0.f; d[mt][nt][2] = 0.f; d[mt][nt][3] = 0.f;
                }
            }
        }
    }
#undef ISSUE_CHUNK
}

// ================= 3) gather-axpy assembly with inline metadata ============
__global__ void __launch_bounds__(512) k_out(const float *__restrict__ bom,
                                             const float *__restrict__ bdcn,
                                             float *__restrict__ out) {
    __shared__ float4 smw[KKN][16];
    __shared__ int4 smi[KKN][16];
    __shared__ float st[16][257];
    int b = blockIdx.y;
    int p0 = blockIdx.x * 16;
    int t = threadIdx.x;

    if (t < KKN * 16) {
        int kk = t >> 4;
        int pl = t & 15;
        int p = p0 + pl;
        int oy = p >> 6, ox = p & 63;
        size_t ob = (size_t)b * 27 * HWP;
#define OMSUM(ch) (g_ompart[0][ob + (size_t)(ch) * HWP + p] + g_ompart[1][ob + (size_t)(ch) * HWP + p] + \
                   g_ompart[2][ob + (size_t)(ch) * HWP + p] + g_ompart[3][ob + (size_t)(ch) * HWP + p] + \
                   g_ompart[4][ob + (size_t)(ch) * HWP + p] + g_ompart[5][ob + (size_t)(ch) * HWP + p] + \
                   g_ompart[6][ob + (size_t)(ch) * HWP + p] + g_ompart[7][ob + (size_t)(ch) * HWP + p])
        float dy = OMSUM(kk) + bom[kk];
        float dx = OMSUM(9 + kk) + bom[9 + kk];
        float mz = OMSUM(18 + kk) + bom[18 + kk];
#undef OMSUM
        float m = 1.f / (1.f + expf(-mz));
        int ki = kk / 3, kj = kk % 3;
        float py = (float)(oy - 1 + ki) + dy;
        float px = (float)(ox - 1 + kj) + dx;
        float y0f = floorf(py), x0f = floorf(px);
        float ly = py - y0f, lx = px - x0f;
        int y0 = (int)y0f, x0 = (int)x0f;
        int y1 = y0 + 1, x1 = x0 + 1;

        float v00 = (y0 >= 0 && y0 < HH && x0 >= 0 && x0 < WW) ? 1.f : 0.f;
        float v01 = (y0 >= 0 && y0 < HH && x1 >= 0 && x1 < WW) ? 1.f : 0.f;
        float v10 = (y1 >= 0 && y1 < HH && x0 >= 0 && x0 < WW) ? 1.f : 0.f;
        float v11 = (y1 >= 0 && y1 < HH && x1 >= 0 && x1 < WW) ? 1.f : 0.f;
        int cy0 = min(max(y0, 0), HH - 1), cy1 = min(max(y1, 0), HH - 1);
        int cx0 = min(max(x0, 0), WW - 1), cx1 = min(max(x1, 0), WW - 1);

        smw[kk][pl] = make_float4((1.f - ly) * (1.f - lx) * m * v00,
                                  (1.f - ly) * lx * m * v01,
                                  ly * (1.f - lx) * m * v10,
                                  ly * lx * m * v11);
        smi[kk][pl] = make_int4((cy0 * WW + cx0) * COUT, (cy0 * WW + cx1) * COUT,
                                (cy1 * WW + cx0) * COUT, (cy1 * WW + cx1) * COUT);
    }
    __syncthreads();

    int pl = t >> 5;
    int ol = (t & 31) * 8;

    u64 a[4];
    {
        float4 b0 = *(const float4 *)(bdcn + ol);
        float4 b1 = *(const float4 *)(bdcn + ol + 4);
        a[0] = pack2(b0.x, b0.y); a[1] = pack2(b0.z, b0.w);
        a[2] = pack2(b1.x, b1.y); a[3] = pack2(b1.z, b1.w);
    }

#define CORNER(W, OFFS) do { \
        u64 ww = pack2((W), (W)); \
        uint4 v = __ldg((const uint4 *)(yk + (OFFS) + ol)); \
        const __half2 *hp = (const __half2 *)&v; \
        _Pragma("unroll") \
        for (int j = 0; j < 4; j++) { \
            float2 f = __half22float2(hp[j]); \
            a[j] = ffma2(pack2(f.x, f.y), ww, a[j]); \
        } \
    } while (0)

#pragma unroll 1
    for (int kk = 0; kk < KKN; kk++) {
        const __half *yk = g_y + (size_t)(kk * BB + b) * HWP * COUT;
        float4 w = smw[kk][pl];
        int4 ii = smi[kk][pl];
        CORNER(w.x, ii.x);
        CORNER(w.y, ii.y);
        CORNER(w.z, ii.z);
        CORNER(w.w, ii.w);
    }
#undef CORNER

    float *sr = &st[pl][ol];
#pragma unroll
    for (int j = 0; j < 4; j++) {
        float lo, hi; unpack2(a[j], lo, hi);
        sr[2 * j] = lo; sr[2 * j + 1] = hi;
    }
    __syncthreads();
    for (int idx = t; idx < 4096; idx += 512) {
        int o = idx >> 4, p2 = idx & 15;
        out[((size_t)b * COUT + o) * HWP + p0 + p2] = st[p2][o];
    }
}

// ---------------- launch ----------------
extern "C" void kernel_launch(void *const *d_in, const int *in_sizes, int n_in,
                              void *d_out, int out_size) {
    const float *x = (const float *)d_in[0];
    const float *w_om = (const float *)d_in[1];
    const float *b_om = (const float *)d_in[2];
    const float *w_dcn = (const float *)d_in[3];
    const float *b_dcn = (const float *)d_in[4];
    float *out = (float *)d_out;

    static int smem_set = 0;
    if (!smem_set) {
        cudaFuncSetAttribute(k_gemm, cudaFuncAttributeMaxDynamicSharedMemorySize, SM_TOT);
        smem_set = 1;
    }

    k_prep<<<NB_PREP, 256>>>(x, w_dcn);

    k_om<<<NB_OM, 256>>>(x, w_om);

    k_gemm<<<NSMG, 256, SM_TOT>>>();

    k_out<<<dim3(HWP / 16, BB), 512>>>(b_om, b_dcn, out);
}